// round 2
// baseline (speedup 1.0000x reference)
#include <cuda_runtime.h>
#include <math.h>

#define B_   2
#define SQ_  2048
#define SK_  2048
#define D_   1024
#define H_   16
#define HD_  64
#define MTOT (B_*SQ_)   // 4096 rows for all GEMMs

// Scratch (allocation-free rule: __device__ globals)
__device__ float g_Q[B_*H_*SQ_*HD_];   // [B,H,SQ,HD]
__device__ float g_K[B_*H_*SK_*HD_];   // [B,H,SK,HD]
__device__ float g_V[B_*H_*SK_*HD_];   // [B,H,SK,HD]
__device__ float g_C[B_*SQ_*D_];       // concat attention output [B*SQ, D]

// ---------------------------------------------------------------------------
// Tiled SGEMM: C[M=4096, N=1024] = A[M,1024] * W + bias
// MODE 0: per-head projection. Column tile bx == head h; W block = W + h*D*HD,
//         ldw = HD, output written in [B,H,S,HD] layout.
// MODE 1: plain GEMM, W row-major [D,D], output [M,D].
// BM=BN=64, BK=16, 256 threads, 4x4 per thread.
// ---------------------------------------------------------------------------
template<int MODE>
__global__ __launch_bounds__(256)
void gemm64(const float* __restrict__ A,
            const float* __restrict__ W,
            const float* __restrict__ bias,
            float* __restrict__ out)
{
    __shared__ float As[16][68];   // [k][m] transposed
    __shared__ float Bs[16][68];   // [k][n]

    const int t  = threadIdx.x;
    const int bx = blockIdx.x;          // 16 column tiles
    const int m0 = blockIdx.y * 64;

    const float* Wb;
    int ldw;
    if (MODE == 0) { Wb = W + (size_t)bx * D_ * HD_; ldw = HD_; }
    else           { Wb = W + bx * 64;               ldw = D_;  }

    const int aRow = t >> 2;            // 0..63
    const int aK4  = (t & 3) * 4;       // 0,4,8,12
    const int wK   = t >> 4;            // 0..15
    const int wN4  = (t & 15) * 4;      // 0..60
    const int tx   = t & 15, ty = t >> 4;

    float acc[4][4] = {};

    for (int k0 = 0; k0 < D_; k0 += 16) {
        float4 av = *(const float4*)&A[(size_t)(m0 + aRow) * D_ + k0 + aK4];
        As[aK4+0][aRow] = av.x; As[aK4+1][aRow] = av.y;
        As[aK4+2][aRow] = av.z; As[aK4+3][aRow] = av.w;
        float4 wv = *(const float4*)&Wb[(size_t)(k0 + wK) * ldw + wN4];
        *(float4*)&Bs[wK][wN4] = wv;
        __syncthreads();
        #pragma unroll
        for (int kk = 0; kk < 16; kk++) {
            float4 a = *(float4*)&As[kk][ty*4];
            float4 b = *(float4*)&Bs[kk][tx*4];
            float ar[4] = {a.x, a.y, a.z, a.w};
            float br[4] = {b.x, b.y, b.z, b.w};
            #pragma unroll
            for (int i = 0; i < 4; i++)
                #pragma unroll
                for (int j = 0; j < 4; j++)
                    acc[i][j] += ar[i] * br[j];
        }
        __syncthreads();
    }

    #pragma unroll
    for (int i = 0; i < 4; i++) {
        const int m = m0 + ty*4 + i;
        #pragma unroll
        for (int j = 0; j < 4; j++) {
            const int nl = tx*4 + j;          // col within tile (== e for MODE 0)
            const int nf = bx*64 + nl;        // flat col (== h*HD+e for MODE 0)
            const float v = acc[i][j] + bias[nf];
            if (MODE == 0) {
                const int b = m >> 11, s = m & 2047;   // SQ_ == SK_ == 2048
                out[(((size_t)(b*H_ + bx))*SQ_ + s)*HD_ + nl] = v;
            } else {
                out[(size_t)m * D_ + nf] = v;
            }
        }
    }
}

// ---------------------------------------------------------------------------
// fp32 flash attention, HD=64. One block = (b, h, 64 q-rows). 256 threads.
// Thread (r = t>>2, g = t&3) owns q-row r and key-columns c = g + 4*i
// (i = 0..15) of each 64-wide K/V chunk; accumulator holds full 64 output
// dims (partial over its c slice), reduced across the quad at the end via
// shfl. c = g+4i interleave keeps all smem reads bank-conflict-free / 2-way.
// ---------------------------------------------------------------------------
#define SPAD 68   // floats per smem row (16B-aligned, conflict-friendly)

__global__ __launch_bounds__(256, 1)
void flash64()
{
    extern __shared__ float sm[];
    float* Qs = sm;                 // [64][SPAD]
    float* Ks = sm +     64*SPAD;   // [64][SPAD]
    float* Vs = sm + 2 * 64*SPAD;   // [64][SPAD]

    const int t  = threadIdx.x;
    const int qt = blockIdx.x;      // 0..31
    const int h  = blockIdx.y;      // 0..15
    const int b  = blockIdx.z;      // 0..1

    const size_t qbase  = (((size_t)b*H_ + h)*SQ_ + qt*64) * HD_;
    const size_t kvbase = (((size_t)b*H_ + h)*SK_) * HD_;

    // Load Q tile (64x64)
    #pragma unroll
    for (int it = 0; it < 4; it++) {
        const int id = t + it*256;          // 0..1023 float4 slots
        const int rr = id >> 4, e4 = (id & 15) * 4;
        float4 v = *(const float4*)&g_Q[qbase + (size_t)rr*HD_ + e4];
        *(float4*)&Qs[rr*SPAD + e4] = v;
    }

    const int r = t >> 2;   // q-row 0..63
    const int g = t & 3;    // quad lane

    float acc[64];
    #pragma unroll
    for (int e = 0; e < 64; e++) acc[e] = 0.f;
    float m_old = -1e30f;
    float lsumT = 0.f;

    for (int c0 = 0; c0 < SK_; c0 += 64) {
        // Load K and V chunks (each 64x64)
        #pragma unroll
        for (int it = 0; it < 4; it++) {
            const int id = t + it*256;
            const int rr = id >> 4, e4 = (id & 15) * 4;
            const size_t goff = kvbase + (size_t)(c0 + rr)*HD_ + e4;
            float4 kv = *(const float4*)&g_K[goff];
            *(float4*)&Ks[rr*SPAD + e4] = kv;
            float4 vv = *(const float4*)&g_V[goff];
            *(float4*)&Vs[rr*SPAD + e4] = vv;
        }
        __syncthreads();

        // S = Q K^T for this thread's 16 columns (c = g + 4*i)
        float s[16];
        #pragma unroll
        for (int i = 0; i < 16; i++) s[i] = 0.f;
        const float4* q4 = (const float4*)(Qs + r*SPAD);
        #pragma unroll
        for (int k4 = 0; k4 < 16; k4++) {
            const float4 q = q4[k4];
            #pragma unroll
            for (int i = 0; i < 16; i++) {
                const float4 kv = *(const float4*)(Ks + (g + 4*i)*SPAD + k4*4);
                s[i] += q.x*kv.x + q.y*kv.y + q.z*kv.z + q.w*kv.w;
            }
        }

        // Online softmax (row stats shared across the quad via shfl)
        float ml = -1e30f;
        #pragma unroll
        for (int i = 0; i < 16; i++) { s[i] *= 0.125f; ml = fmaxf(ml, s[i]); }
        ml = fmaxf(ml, __shfl_xor_sync(0xffffffffu, ml, 1));
        ml = fmaxf(ml, __shfl_xor_sync(0xffffffffu, ml, 2));
        const float m_new  = fmaxf(m_old, ml);
        const float factor = __expf(m_old - m_new);
        float ls = 0.f;
        #pragma unroll
        for (int i = 0; i < 16; i++) { s[i] = __expf(s[i] - m_new); ls += s[i]; }
        ls += __shfl_xor_sync(0xffffffffu, ls, 1);
        ls += __shfl_xor_sync(0xffffffffu, ls, 2);
        lsumT = lsumT * factor + ls;
        m_old = m_new;

        #pragma unroll
        for (int e = 0; e < 64; e++) acc[e] *= factor;

        // acc += P * V over this thread's c slice
        #pragma unroll
        for (int i = 0; i < 16; i++) {
            const float pv = s[i];
            const float4* vr = (const float4*)(Vs + (g + 4*i)*SPAD);
            #pragma unroll
            for (int e4 = 0; e4 < 16; e4++) {
                const float4 v = vr[e4];
                acc[e4*4+0] += pv * v.x;
                acc[e4*4+1] += pv * v.y;
                acc[e4*4+2] += pv * v.z;
                acc[e4*4+3] += pv * v.w;
            }
        }
        __syncthreads();
    }

    // Reduce partial accumulators across the quad
    #pragma unroll
    for (int e = 0; e < 64; e++) {
        acc[e] += __shfl_xor_sync(0xffffffffu, acc[e], 1);
        acc[e] += __shfl_xor_sync(0xffffffffu, acc[e], 2);
    }
    const float inv = 1.f / lsumT;

    if (g == 0) {
        float* op = g_C + ((size_t)(b*SQ_ + qt*64 + r))*D_ + h*HD_;
        #pragma unroll
        for (int e4 = 0; e4 < 16; e4++) {
            float4 v = make_float4(acc[e4*4+0]*inv, acc[e4*4+1]*inv,
                                   acc[e4*4+2]*inv, acc[e4*4+3]*inv);
            *(float4*)&op[e4*4] = v;
        }
    }
}

// ---------------------------------------------------------------------------
extern "C" void kernel_launch(void* const* d_in, const int* in_sizes, int n_in,
                              void* d_out, int out_size)
{
    const float* x   = (const float*)d_in[0];
    const float* enc = (const float*)d_in[1];
    const float* Wq  = (const float*)d_in[2];
    const float* bq  = (const float*)d_in[3];
    const float* Wk  = (const float*)d_in[4];
    const float* bk  = (const float*)d_in[5];
    const float* Wv  = (const float*)d_in[6];
    const float* bv  = (const float*)d_in[7];
    const float* Wo  = (const float*)d_in[8];
    const float* bo  = (const float*)d_in[9];

    float *Qp, *Kp, *Vp, *Cp;
    cudaGetSymbolAddress((void**)&Qp, g_Q);
    cudaGetSymbolAddress((void**)&Kp, g_K);
    cudaGetSymbolAddress((void**)&Vp, g_V);
    cudaGetSymbolAddress((void**)&Cp, g_C);

    const int flash_smem = 3 * 64 * SPAD * (int)sizeof(float);   // 52224 B
    cudaFuncSetAttribute(flash64, cudaFuncAttributeMaxDynamicSharedMemorySize,
                         flash_smem);

    dim3 gthr(256);
    dim3 ggrid(16, MTOT / 64);   // (16, 64)

    gemm64<0><<<ggrid, gthr>>>(x,   Wq, bq, Qp);
    gemm64<0><<<ggrid, gthr>>>(enc, Wk, bk, Kp);
    gemm64<0><<<ggrid, gthr>>>(enc, Wv, bv, Vp);

    flash64<<<dim3(SQ_/64, H_, B_), 256, flash_smem>>>();

    gemm64<1><<<ggrid, gthr>>>(Cp, Wo, bo, (float*)d_out);
}

// round 6
// speedup vs baseline: 4.0186x; 4.0186x over previous
#include <cuda_runtime.h>
#include <cuda_fp16.h>
#include <cstdint>
#include <math.h>

#define B_   2
#define SQ_  2048
#define SK_  2048
#define D_   1024
#define H_   16
#define HD_  64
#define MTOT (B_*SQ_)   // 4096 rows for all GEMMs

// Scratch (allocation-free rule: __device__ globals)
__device__ float g_Q[B_*H_*SQ_*HD_];   // [B,H,SQ,HD]
__device__ float g_K[B_*H_*SK_*HD_];   // [B,H,SK,HD]
__device__ float g_V[B_*H_*SK_*HD_];   // [B,H,SK,HD]
__device__ float g_C[B_*SQ_*D_];       // concat attention output [B*SQ, D]

// ---------------------------------------------------------------------------
// mma helpers
// ---------------------------------------------------------------------------
__device__ __forceinline__ uint32_t f2tf32(float x) {
    uint32_t r;
    asm("cvt.rna.tf32.f32 %0, %1;" : "=r"(r) : "f"(x));
    return r;
}

__device__ __forceinline__ void mma_tf32(float c[4], const uint32_t a[4],
                                         uint32_t b0, uint32_t b1) {
    asm volatile(
        "mma.sync.aligned.m16n8k8.row.col.f32.tf32.tf32.f32 "
        "{%0,%1,%2,%3}, {%4,%5,%6,%7}, {%8,%9}, {%0,%1,%2,%3};"
        : "+f"(c[0]), "+f"(c[1]), "+f"(c[2]), "+f"(c[3])
        : "r"(a[0]), "r"(a[1]), "r"(a[2]), "r"(a[3]), "r"(b0), "r"(b1));
}

__device__ __forceinline__ void mma_f16(float c[4], const uint32_t a[4],
                                        uint32_t b0, uint32_t b1) {
    asm volatile(
        "mma.sync.aligned.m16n8k16.row.col.f32.f16.f16.f32 "
        "{%0,%1,%2,%3}, {%4,%5,%6,%7}, {%8,%9}, {%0,%1,%2,%3};"
        : "+f"(c[0]), "+f"(c[1]), "+f"(c[2]), "+f"(c[3])
        : "r"(a[0]), "r"(a[1]), "r"(a[2]), "r"(a[3]), "r"(b0), "r"(b1));
}

__device__ __forceinline__ void ldmatrix_x4_trans(uint32_t& r0, uint32_t& r1,
                                                  uint32_t& r2, uint32_t& r3,
                                                  uint32_t addr) {
    asm volatile(
        "ldmatrix.sync.aligned.m8n8.x4.trans.shared.b16 {%0,%1,%2,%3}, [%4];"
        : "=r"(r0), "=r"(r1), "=r"(r2), "=r"(r3) : "r"(addr));
}

// ---------------------------------------------------------------------------
// tf32 mma GEMM: C[4096, 1024] = A[4096,1024] * W + bias
// MODE 0: per-head projection (bx == head), W block ldw=HD, out [B,H,S,HD].
// MODE 1: plain GEMM, W row-major [D,D], out [M,D].
// Block tile 64x64, BK=16, 128 threads (4 warps x 16 rows).
// ---------------------------------------------------------------------------
#define ASTR 20   // As row stride (uint), conflict-free for A frags
#define WSTR 68   // Ws row stride (uint)

template<int MODE>
__global__ __launch_bounds__(128)
void gemm_mma(const float* __restrict__ A,
              const float* __restrict__ W,
              const float* __restrict__ bias,
              float* __restrict__ out)
{
    __shared__ uint32_t As[64 * ASTR];
    __shared__ uint32_t Ws[16 * WSTR];

    const int t    = threadIdx.x;
    const int lane = t & 31;
    const int wid  = t >> 5;
    const int gid  = lane >> 2;   // 0..7
    const int tid4 = lane & 3;    // 0..3
    const int w16  = wid * 16;

    const int bx = blockIdx.x;           // 16 column tiles
    const int m0 = blockIdx.y * 64;

    const float* Wb;
    int ldw;
    if (MODE == 0) { Wb = W + (size_t)bx * D_ * HD_; ldw = HD_; }
    else           { Wb = W + bx * 64;               ldw = D_;  }

    float c[8][4];
    #pragma unroll
    for (int j = 0; j < 8; j++)
        #pragma unroll
        for (int i = 0; i < 4; i++) c[j][i] = 0.f;

    for (int k0 = 0; k0 < D_; k0 += 16) {
        // Stage A tile 64x16 (tf32)
        #pragma unroll
        for (int it = 0; it < 2; it++) {
            const int id  = t + it * 128;       // 0..255
            const int row = id >> 2, c4 = (id & 3) * 4;
            float4 av = *(const float4*)&A[(size_t)(m0 + row) * D_ + k0 + c4];
            uint4 u = make_uint4(f2tf32(av.x), f2tf32(av.y),
                                 f2tf32(av.z), f2tf32(av.w));
            *(uint4*)&As[row * ASTR + c4] = u;
        }
        // Stage W tile 16x64 (tf32)
        #pragma unroll
        for (int it = 0; it < 2; it++) {
            const int id  = t + it * 128;
            const int row = id >> 4, c4 = (id & 15) * 4;
            float4 wv = *(const float4*)&Wb[(size_t)(k0 + row) * ldw + c4];
            uint4 u = make_uint4(f2tf32(wv.x), f2tf32(wv.y),
                                 f2tf32(wv.z), f2tf32(wv.w));
            *(uint4*)&Ws[row * WSTR + c4] = u;
        }
        __syncthreads();

        #pragma unroll
        for (int ks = 0; ks < 2; ks++) {
            uint32_t a[4];
            a[0] = As[(w16 + gid    ) * ASTR + ks * 8 + tid4    ];
            a[1] = As[(w16 + gid + 8) * ASTR + ks * 8 + tid4    ];
            a[2] = As[(w16 + gid    ) * ASTR + ks * 8 + tid4 + 4];
            a[3] = As[(w16 + gid + 8) * ASTR + ks * 8 + tid4 + 4];
            #pragma unroll
            for (int j = 0; j < 8; j++) {
                uint32_t b0 = Ws[(ks * 8 + tid4    ) * WSTR + j * 8 + gid];
                uint32_t b1 = Ws[(ks * 8 + tid4 + 4) * WSTR + j * 8 + gid];
                mma_tf32(c[j], a, b0, b1);
            }
        }
        __syncthreads();
    }

    // Epilogue: rows m0+w16+gid (+8), cols j*8 + 2*tid4 (+1)
    #pragma unroll
    for (int half = 0; half < 2; half++) {
        const int m = m0 + w16 + gid + half * 8;
        #pragma unroll
        for (int j = 0; j < 8; j++) {
            const int nl = j * 8 + tid4 * 2;
            const int nf = bx * 64 + nl;
            float2 v;
            v.x = c[j][half * 2 + 0] + bias[nf];
            v.y = c[j][half * 2 + 1] + bias[nf + 1];
            if (MODE == 0) {
                const int b = m >> 11, s = m & 2047;
                *(float2*)&out[(((size_t)(b * H_ + bx)) * SQ_ + s) * HD_ + nl] = v;
            } else {
                *(float2*)&out[(size_t)m * D_ + nf] = v;
            }
        }
    }
}

// ---------------------------------------------------------------------------
// Flash attention via mma. Block = (b, h, 64 q rows), 4 warps x 16 q rows.
// QK^T: tf32 m16n8k8 (Q frags hoisted to registers, loop-invariant).
// softmax on C fragments (quad shfl for row stats).
// P*V: fp16 m16n8k16; P packed from C regs (layout-exact), V via ldmatrix.trans.
// ---------------------------------------------------------------------------
#define QSTR 68   // Qs/Ks stride (uint32)
#define VSTR 72   // Vs stride (halfs)

__global__ __launch_bounds__(128)
void flash_mma()
{
    __shared__ uint32_t Qs[64 * QSTR];
    __shared__ uint32_t Ks[64 * QSTR];
    __shared__ __half   Vs[64 * VSTR];

    const int t    = threadIdx.x;
    const int lane = t & 31;
    const int wid  = t >> 5;
    const int gid  = lane >> 2;   // row group 0..7
    const int tid4 = lane & 3;
    const int w16  = wid * 16;

    const int qt = blockIdx.x;    // 0..31
    const int h  = blockIdx.y;
    const int b  = blockIdx.z;

    const size_t qbase  = (((size_t)b * H_ + h) * SQ_ + qt * 64) * HD_;
    const size_t kvbase = (((size_t)b * H_ + h) * SK_) * HD_;

    // Stage Q (x 1/8 softmax scale folded in, exact pow2), tf32
    #pragma unroll
    for (int it = 0; it < 8; it++) {
        const int id = t + it * 128;           // 0..1023 float4 slots
        const int rr = id >> 4, c4 = (id & 15) * 4;
        float4 v = *(const float4*)&g_Q[qbase + (size_t)rr * HD_ + c4];
        uint4 u = make_uint4(f2tf32(v.x * 0.125f), f2tf32(v.y * 0.125f),
                             f2tf32(v.z * 0.125f), f2tf32(v.w * 0.125f));
        *(uint4*)&Qs[rr * QSTR + c4] = u;
    }
    __syncthreads();

    // Hoist Q fragments: loop-invariant across all KV chunks
    uint32_t aQ[8][4];
    #pragma unroll
    for (int k = 0; k < 8; k++) {
        aQ[k][0] = Qs[(w16 + gid    ) * QSTR + k * 8 + tid4    ];
        aQ[k][1] = Qs[(w16 + gid + 8) * QSTR + k * 8 + tid4    ];
        aQ[k][2] = Qs[(w16 + gid    ) * QSTR + k * 8 + tid4 + 4];
        aQ[k][3] = Qs[(w16 + gid + 8) * QSTR + k * 8 + tid4 + 4];
    }

    const uint32_t vsb = (uint32_t)__cvta_generic_to_shared(Vs);

    float cO[8][4];
    #pragma unroll
    for (int j = 0; j < 8; j++)
        #pragma unroll
        for (int i = 0; i < 4; i++) cO[j][i] = 0.f;
    float m0 = -1e30f, m1 = -1e30f, l0 = 0.f, l1 = 0.f;

    for (int c0 = 0; c0 < SK_; c0 += 64) {
        // Stage K (tf32) and V (fp16)
        #pragma unroll
        for (int it = 0; it < 8; it++) {
            const int id = t + it * 128;
            const int rr = id >> 4, c4 = (id & 15) * 4;
            const size_t goff = kvbase + (size_t)(c0 + rr) * HD_ + c4;
            float4 kv = *(const float4*)&g_K[goff];
            uint4 u = make_uint4(f2tf32(kv.x), f2tf32(kv.y),
                                 f2tf32(kv.z), f2tf32(kv.w));
            *(uint4*)&Ks[rr * QSTR + c4] = u;
            float4 vv = *(const float4*)&g_V[goff];
            __half2 h01 = __floats2half2_rn(vv.x, vv.y);
            __half2 h23 = __floats2half2_rn(vv.z, vv.w);
            uint2 vu = make_uint2(reinterpret_cast<uint32_t&>(h01),
                                  reinterpret_cast<uint32_t&>(h23));
            *(uint2*)&Vs[rr * VSTR + c4] = vu;
        }
        __syncthreads();

        // S = Q K^T (tf32 mma), warp computes 16x64
        float cS[8][4];
        #pragma unroll
        for (int j = 0; j < 8; j++)
            #pragma unroll
            for (int i = 0; i < 4; i++) cS[j][i] = 0.f;

        #pragma unroll
        for (int k = 0; k < 8; k++) {
            #pragma unroll
            for (int j = 0; j < 8; j++) {
                uint32_t b0 = Ks[(j * 8 + gid) * QSTR + k * 8 + tid4    ];
                uint32_t b1 = Ks[(j * 8 + gid) * QSTR + k * 8 + tid4 + 4];
                mma_tf32(cS[j], aQ[k], b0, b1);
            }
        }

        // Online softmax on fragments (rows gid and gid+8)
        float mx0 = -1e30f, mx1 = -1e30f;
        #pragma unroll
        for (int j = 0; j < 8; j++) {
            mx0 = fmaxf(mx0, fmaxf(cS[j][0], cS[j][1]));
            mx1 = fmaxf(mx1, fmaxf(cS[j][2], cS[j][3]));
        }
        mx0 = fmaxf(mx0, __shfl_xor_sync(0xffffffffu, mx0, 1));
        mx0 = fmaxf(mx0, __shfl_xor_sync(0xffffffffu, mx0, 2));
        mx1 = fmaxf(mx1, __shfl_xor_sync(0xffffffffu, mx1, 1));
        mx1 = fmaxf(mx1, __shfl_xor_sync(0xffffffffu, mx1, 2));
        const float nm0 = fmaxf(m0, mx0), nm1 = fmaxf(m1, mx1);
        const float f0 = __expf(m0 - nm0), f1 = __expf(m1 - nm1);
        m0 = nm0; m1 = nm1;

        float s0 = 0.f, s1 = 0.f;
        uint32_t ph[8][2];
        #pragma unroll
        for (int j = 0; j < 8; j++) {
            float p0 = __expf(cS[j][0] - m0);
            float p1 = __expf(cS[j][1] - m0);
            float p2 = __expf(cS[j][2] - m1);
            float p3 = __expf(cS[j][3] - m1);
            s0 += p0 + p1;  s1 += p2 + p3;
            __half2 h01 = __floats2half2_rn(p0, p1);
            __half2 h23 = __floats2half2_rn(p2, p3);
            ph[j][0] = reinterpret_cast<uint32_t&>(h01);
            ph[j][1] = reinterpret_cast<uint32_t&>(h23);
        }
        s0 += __shfl_xor_sync(0xffffffffu, s0, 1);
        s0 += __shfl_xor_sync(0xffffffffu, s0, 2);
        s1 += __shfl_xor_sync(0xffffffffu, s1, 1);
        s1 += __shfl_xor_sync(0xffffffffu, s1, 2);
        l0 = l0 * f0 + s0;
        l1 = l1 * f1 + s1;

        #pragma unroll
        for (int j = 0; j < 8; j++) {
            cO[j][0] *= f0; cO[j][1] *= f0;
            cO[j][2] *= f1; cO[j][3] *= f1;
        }

        // O += P * V  (fp16 mma; P fragments come straight from cS layout)
        #pragma unroll
        for (int tk = 0; tk < 4; tk++) {
            uint32_t aP[4] = { ph[2*tk][0], ph[2*tk][1],
                               ph[2*tk+1][0], ph[2*tk+1][1] };
            #pragma unroll
            for (int jp = 0; jp < 4; jp++) {
                const int vrow = tk * 16 + (lane & 15);
                const int vcol = (lane >> 4) * 8 + jp * 16;
                uint32_t addr = vsb + (uint32_t)(vrow * VSTR + vcol) * 2u;
                uint32_t r0, r1, r2, r3;
                ldmatrix_x4_trans(r0, r1, r2, r3, addr);
                mma_f16(cO[2*jp    ], aP, r0, r1);
                mma_f16(cO[2*jp + 1], aP, r2, r3);
            }
        }
        __syncthreads();
    }

    // Epilogue: normalize and store to concat layout [B*SQ, D]
    const float inv0 = 1.f / l0;
    const float inv1 = 1.f / l1;
    const int qrow = qt * 64 + w16 + gid;
    float* op0 = g_C + ((size_t)(b * SQ_ + qrow    )) * D_ + h * HD_;
    float* op1 = g_C + ((size_t)(b * SQ_ + qrow + 8)) * D_ + h * HD_;
    #pragma unroll
    for (int j = 0; j < 8; j++) {
        const int nl = j * 8 + tid4 * 2;
        float2 v0 = make_float2(cO[j][0] * inv0, cO[j][1] * inv0);
        float2 v1 = make_float2(cO[j][2] * inv1, cO[j][3] * inv1);
        *(float2*)&op0[nl] = v0;
        *(float2*)&op1[nl] = v1;
    }
}

// ---------------------------------------------------------------------------
extern "C" void kernel_launch(void* const* d_in, const int* in_sizes, int n_in,
                              void* d_out, int out_size)
{
    const float* x   = (const float*)d_in[0];
    const float* enc = (const float*)d_in[1];
    const float* Wq  = (const float*)d_in[2];
    const float* bq  = (const float*)d_in[3];
    const float* Wk  = (const float*)d_in[4];
    const float* bk  = (const float*)d_in[5];
    const float* Wv  = (const float*)d_in[6];
    const float* bv  = (const float*)d_in[7];
    const float* Wo  = (const float*)d_in[8];
    const float* bo  = (const float*)d_in[9];

    float *Qp, *Kp, *Vp, *Cp;
    cudaGetSymbolAddress((void**)&Qp, g_Q);
    cudaGetSymbolAddress((void**)&Kp, g_K);
    cudaGetSymbolAddress((void**)&Vp, g_V);
    cudaGetSymbolAddress((void**)&Cp, g_C);

    dim3 gthr(128);
    dim3 ggrid(16, MTOT / 64);   // (16, 64)

    gemm_mma<0><<<ggrid, gthr>>>(x,   Wq, bq, Qp);
    gemm_mma<0><<<ggrid, gthr>>>(enc, Wk, bk, Kp);
    gemm_mma<0><<<ggrid, gthr>>>(enc, Wv, bv, Vp);

    flash_mma<<<dim3(SQ_/64, H_, B_), 128>>>();

    gemm_mma<1><<<ggrid, gthr>>>(Cp, Wo, bo, (float*)d_out);
}

// round 7
// speedup vs baseline: 8.0141x; 1.9943x over previous
#include <cuda_runtime.h>
#include <cuda_fp16.h>
#include <cstdint>
#include <math.h>

#define B_   2
#define SQ_  2048
#define SK_  2048
#define D_   1024
#define H_   16
#define HD_  64
#define MTOT (B_*SQ_)   // 4096

#define QSCALE (0.125f * 1.4426950408889634f)   // softmax scale * log2(e)

// ---------------------------------------------------------------------------
// fp16 scratch (allocation-free rule: __device__ globals)
// ---------------------------------------------------------------------------
__device__ __half g_xh [MTOT*D_];        // x in fp16
__device__ __half g_eh [MTOT*D_];        // encoder_output in fp16
__device__ __half g_Wqh[H_*HD_*D_];      // per-head [h][n][k] fp16 (transposed)
__device__ __half g_Wkh[H_*HD_*D_];
__device__ __half g_Wvh[H_*HD_*D_];
__device__ __half g_Woh[D_*D_];          // [n][k] fp16 (transposed)
__device__ __half g_Q  [B_*H_*SQ_*HD_];  // [B,H,SQ,HD], pre-scaled by QSCALE
__device__ __half g_K  [B_*H_*SK_*HD_];
__device__ __half g_V  [B_*H_*SK_*HD_];
__device__ __half g_C  [B_*SQ_*D_];      // concat attention out [B*SQ, D]

// ---------------------------------------------------------------------------
// helpers
// ---------------------------------------------------------------------------
__device__ __forceinline__ void mma_f16(float c[4], const uint32_t a[4],
                                        uint32_t b0, uint32_t b1) {
    asm volatile(
        "mma.sync.aligned.m16n8k16.row.col.f32.f16.f16.f32 "
        "{%0,%1,%2,%3}, {%4,%5,%6,%7}, {%8,%9}, {%0,%1,%2,%3};"
        : "+f"(c[0]), "+f"(c[1]), "+f"(c[2]), "+f"(c[3])
        : "r"(a[0]), "r"(a[1]), "r"(a[2]), "r"(a[3]), "r"(b0), "r"(b1));
}

__device__ __forceinline__ void ldmatrix_x4_trans(uint32_t& r0, uint32_t& r1,
                                                  uint32_t& r2, uint32_t& r3,
                                                  uint32_t addr) {
    asm volatile(
        "ldmatrix.sync.aligned.m8n8.x4.trans.shared.b16 {%0,%1,%2,%3}, [%4];"
        : "=r"(r0), "=r"(r1), "=r"(r2), "=r"(r3) : "r"(addr));
}

__device__ __forceinline__ void cp16(uint32_t dst, const void* src) {
    asm volatile("cp.async.ca.shared.global [%0], [%1], 16;\n"
                 :: "r"(dst), "l"(src));
}
__device__ __forceinline__ void cp_commit() {
    asm volatile("cp.async.commit_group;\n");
}
template<int N> __device__ __forceinline__ void cp_wait() {
    asm volatile("cp.async.wait_group %0;\n" :: "n"(N));
}

__device__ __forceinline__ float ex2(float x) {
    float r;
    asm("ex2.approx.f32 %0, %1;" : "=f"(r) : "f"(x));
    return r;
}

__device__ __forceinline__ uint32_t packh2(float a, float b) {
    __half2 h = __floats2half2_rn(a, b);
    return *reinterpret_cast<uint32_t*>(&h);
}

// ---------------------------------------------------------------------------
// prepass 1: f32 -> fp16 elementwise (count = multiple of 1024 float4s)
// ---------------------------------------------------------------------------
__global__ __launch_bounds__(256)
void cvt_f2h(const float* __restrict__ in, __half* __restrict__ out) {
    const int i = blockIdx.x * 256 + threadIdx.x;
    float4 v = ((const float4*)in)[i];
    uint2 u;
    u.x = packh2(v.x, v.y);
    u.y = packh2(v.z, v.w);
    ((uint2*)out)[i] = u;
}

// ---------------------------------------------------------------------------
// prepass 2: transpose + convert. in f32 [R,C] -> out fp16 [C,R].
// grid (C/32, R/32, Z); per-z offset R*C. block = 256 (32x8 logical).
// ---------------------------------------------------------------------------
__global__ __launch_bounds__(256)
void tr_cvt(const float* __restrict__ in, __half* __restrict__ out,
            int R, int C) {
    __shared__ float tile[32][33];
    in  += (size_t)blockIdx.z * R * C;
    out += (size_t)blockIdx.z * R * C;
    const int c0 = blockIdx.x * 32, r0 = blockIdx.y * 32;
    const int tx = threadIdx.x & 31, ty = threadIdx.x >> 5;
    #pragma unroll
    for (int i = 0; i < 32; i += 8)
        tile[ty + i][tx] = in[(size_t)(r0 + ty + i) * C + c0 + tx];
    __syncthreads();
    #pragma unroll
    for (int i = 0; i < 32; i += 8)
        out[(size_t)(c0 + ty + i) * R + r0 + tx] =
            __float2half_rn(tile[tx][ty + i]);
}

// ---------------------------------------------------------------------------
// fp16 GEMM: out[M=4096, 1024-col-tile bx] = A[M,1024] * Wh[bx]^T + bias
// A: fp16 [M,1024] row-major.  Wh: fp16 [n][k] per 64-col tile (bx*64*1024).
// Tile 128x64, 8 warps, BK=32, 2-stage cp.async pipeline.
// EPI 0: out = half [B,H,S,HD] at head bx, value (acc+bias)*scale.
// EPI 1: out = f32 flat [M,D], value acc+bias.
// ---------------------------------------------------------------------------
#define ASW 20   // As row stride in words (40 halfs)
#define WSW 20   // Ws row stride in words

template<int EPI>
__global__ __launch_bounds__(256)
void gemm_h(const __half* __restrict__ A, const __half* __restrict__ Wh,
            const float* __restrict__ bias, void* __restrict__ outv,
            float scale)
{
    __shared__ uint32_t As[2][128 * ASW];
    __shared__ uint32_t Ws[2][64 * WSW];

    const int t    = threadIdx.x;
    const int lane = t & 31, wid = t >> 5;
    const int gid  = lane >> 2, tid4 = lane & 3;
    const int w16  = wid * 16;
    const int bx   = blockIdx.x;           // 16 column tiles
    const int m0   = blockIdx.y * 128;

    const __half* Wb = Wh + (size_t)bx * 64 * D_;

    const uint32_t asb = (uint32_t)__cvta_generic_to_shared(&As[0][0]);
    const uint32_t wsb = (uint32_t)__cvta_generic_to_shared(&Ws[0][0]);

    auto stage = [&](int buf, int k0) {
        #pragma unroll
        for (int it = 0; it < 2; it++) {              // A: 128x32 halfs
            const int id  = t + it * 256;
            const int row = id >> 2, c8 = (id & 3) * 8;
            cp16(asb + (uint32_t)(buf * 128 * ASW + row * ASW + (id & 3) * 4) * 4,
                 A + (size_t)(m0 + row) * D_ + k0 + c8);
        }
        {                                             // W: 64x32 halfs
            const int row = t >> 2, c8 = (t & 3) * 8;
            cp16(wsb + (uint32_t)(buf * 64 * WSW + row * WSW + (t & 3) * 4) * 4,
                 Wb + (size_t)row * D_ + k0 + c8);
        }
    };

    float c[8][4];
    #pragma unroll
    for (int j = 0; j < 8; j++)
        #pragma unroll
        for (int i = 0; i < 4; i++) c[j][i] = 0.f;

    stage(0, 0);
    cp_commit();

    for (int kc = 0; kc < 32; kc++) {
        if (kc + 1 < 32) { stage((kc + 1) & 1, (kc + 1) * 32); cp_commit(); cp_wait<1>(); }
        else             { cp_wait<0>(); }
        __syncthreads();

        const uint32_t* Ab = As[kc & 1];
        const uint32_t* Bb = Ws[kc & 1];
        #pragma unroll
        for (int ks = 0; ks < 2; ks++) {
            uint32_t a[4];
            a[0] = Ab[(w16 + gid    ) * ASW + ks * 8 + tid4    ];
            a[1] = Ab[(w16 + gid + 8) * ASW + ks * 8 + tid4    ];
            a[2] = Ab[(w16 + gid    ) * ASW + ks * 8 + tid4 + 4];
            a[3] = Ab[(w16 + gid + 8) * ASW + ks * 8 + tid4 + 4];
            #pragma unroll
            for (int j = 0; j < 8; j++) {
                uint32_t b0 = Bb[(j * 8 + gid) * WSW + ks * 8 + tid4    ];
                uint32_t b1 = Bb[(j * 8 + gid) * WSW + ks * 8 + tid4 + 4];
                mma_f16(c[j], a, b0, b1);
            }
        }
        __syncthreads();
    }

    // Epilogue
    #pragma unroll
    for (int hh = 0; hh < 2; hh++) {
        const int m = m0 + w16 + gid + hh * 8;
        #pragma unroll
        for (int j = 0; j < 8; j++) {
            const int nl = j * 8 + tid4 * 2;
            const int nf = bx * 64 + nl;
            const float v0 = c[j][hh * 2 + 0] + bias[nf];
            const float v1 = c[j][hh * 2 + 1] + bias[nf + 1];
            if (EPI == 0) {
                __half* out = (__half*)outv;
                const int bI = m >> 11, s = m & 2047;
                uint32_t hv = packh2(v0 * scale, v1 * scale);
                *(uint32_t*)&out[(((size_t)(bI * H_ + bx)) * SQ_ + s) * HD_ + nl] = hv;
            } else {
                float* out = (float*)outv;
                *(float2*)&out[(size_t)m * D_ + nf] = make_float2(v0, v1);
            }
        }
    }
}

// ---------------------------------------------------------------------------
// Flash attention, fp16 mma. Block = (b, h, 128 q rows), 8 warps.
// Q staged once (cp.async) into the ping-pong region, frags hoisted to regs.
// K/V double-buffered via cp.async. Softmax in base-2 (Q pre-scaled by
// 0.125*log2e at projection time). P*V: fp16 mma, V via ldmatrix.trans.
// smem pool (words): Q stage [0,4608) == Ks0|Ks1; Ks[buf]=buf*2304;
// Vs[buf]=4608+buf*2304. Row strides: K/Q 36 words (72 halfs), V 72 halfs.
// ---------------------------------------------------------------------------
__global__ __launch_bounds__(256)
void flash_h()
{
    __shared__ uint32_t pool[9216];   // 36,864 B

    const int t    = threadIdx.x;
    const int lane = t & 31, wid = t >> 5;
    const int gid  = lane >> 2, tid4 = lane & 3;
    const int w16  = wid * 16;

    const int qt = blockIdx.x;        // 0..15
    const int h  = blockIdx.y;
    const int b  = blockIdx.z;

    const size_t qbase  = (((size_t)b * H_ + h) * SQ_ + qt * 128) * HD_;
    const size_t kvbase = (((size_t)b * H_ + h) * SK_) * HD_;

    const uint32_t pb = (uint32_t)__cvta_generic_to_shared(pool);

    // Stage Q (128x64 halfs) into pool[0..4608)
    #pragma unroll
    for (int it = 0; it < 4; it++) {
        const int id  = t + it * 256;
        const int row = id >> 3, c8 = (id & 7) * 8;
        cp16(pb + (uint32_t)(row * 36 + (id & 7) * 4) * 4,
             g_Q + qbase + (size_t)row * HD_ + c8);
    }
    cp_commit(); cp_wait<0>();
    __syncthreads();

    // Hoist Q fragments (loop-invariant)
    uint32_t aQ[4][4];
    #pragma unroll
    for (int ks = 0; ks < 4; ks++) {
        aQ[ks][0] = pool[(w16 + gid    ) * 36 + ks * 8 + tid4    ];
        aQ[ks][1] = pool[(w16 + gid + 8) * 36 + ks * 8 + tid4    ];
        aQ[ks][2] = pool[(w16 + gid    ) * 36 + ks * 8 + tid4 + 4];
        aQ[ks][3] = pool[(w16 + gid + 8) * 36 + ks * 8 + tid4 + 4];
    }
    __syncthreads();   // everyone done reading Q before pipeline overwrites

    float cO[8][4];
    #pragma unroll
    for (int j = 0; j < 8; j++)
        #pragma unroll
        for (int i = 0; i < 4; i++) cO[j][i] = 0.f;
    float m0 = -1e30f, m1 = -1e30f, l0 = 0.f, l1 = 0.f;

    auto stageKV = [&](int buf, int c0) {
        #pragma unroll
        for (int it = 0; it < 2; it++) {
            const int id  = t + it * 256;
            const int row = id >> 3, c8 = (id & 7) * 8;
            const size_t go = kvbase + (size_t)(c0 + row) * HD_ + c8;
            cp16(pb + (uint32_t)(       buf * 2304 + row * 36 + (id & 7) * 4) * 4,
                 g_K + go);
            cp16(pb + (uint32_t)(4608 + buf * 2304 + row * 36 + (id & 7) * 4) * 4,
                 g_V + go);
        }
    };

    stageKV(0, 0);
    cp_commit();

    for (int cc = 0; cc < 32; cc++) {
        if (cc + 1 < 32) { stageKV((cc + 1) & 1, (cc + 1) * 64); cp_commit(); cp_wait<1>(); }
        else             { cp_wait<0>(); }
        __syncthreads();

        const uint32_t* Ks = pool + (cc & 1) * 2304;
        const uint32_t  vsb = pb + (uint32_t)(4608 + (cc & 1) * 2304) * 4;

        // S = Q K^T (fp16 mma k16)
        float cS[8][4];
        #pragma unroll
        for (int j = 0; j < 8; j++)
            #pragma unroll
            for (int i = 0; i < 4; i++) cS[j][i] = 0.f;

        #pragma unroll
        for (int ks = 0; ks < 4; ks++) {
            #pragma unroll
            for (int j = 0; j < 8; j++) {
                uint32_t b0 = Ks[(j * 8 + gid) * 36 + ks * 8 + tid4    ];
                uint32_t b1 = Ks[(j * 8 + gid) * 36 + ks * 8 + tid4 + 4];
                mma_f16(cS[j], aQ[ks], b0, b1);
            }
        }

        // Online softmax, base-2 (scores already include log2e factor)
        float mx0 = -1e30f, mx1 = -1e30f;
        #pragma unroll
        for (int j = 0; j < 8; j++) {
            mx0 = fmaxf(mx0, fmaxf(cS[j][0], cS[j][1]));
            mx1 = fmaxf(mx1, fmaxf(cS[j][2], cS[j][3]));
        }
        mx0 = fmaxf(mx0, __shfl_xor_sync(0xffffffffu, mx0, 1));
        mx0 = fmaxf(mx0, __shfl_xor_sync(0xffffffffu, mx0, 2));
        mx1 = fmaxf(mx1, __shfl_xor_sync(0xffffffffu, mx1, 1));
        mx1 = fmaxf(mx1, __shfl_xor_sync(0xffffffffu, mx1, 2));
        const float nm0 = fmaxf(m0, mx0), nm1 = fmaxf(m1, mx1);
        const float f0 = ex2(m0 - nm0), f1 = ex2(m1 - nm1);
        m0 = nm0; m1 = nm1;

        float s0 = 0.f, s1 = 0.f;
        uint32_t ph[8][2];
        #pragma unroll
        for (int j = 0; j < 8; j++) {
            const float p0 = ex2(cS[j][0] - m0);
            const float p1 = ex2(cS[j][1] - m0);
            const float p2 = ex2(cS[j][2] - m1);
            const float p3 = ex2(cS[j][3] - m1);
            s0 += p0 + p1;  s1 += p2 + p3;
            ph[j][0] = packh2(p0, p1);
            ph[j][1] = packh2(p2, p3);
        }
        s0 += __shfl_xor_sync(0xffffffffu, s0, 1);
        s0 += __shfl_xor_sync(0xffffffffu, s0, 2);
        s1 += __shfl_xor_sync(0xffffffffu, s1, 1);
        s1 += __shfl_xor_sync(0xffffffffu, s1, 2);
        l0 = l0 * f0 + s0;
        l1 = l1 * f1 + s1;

        #pragma unroll
        for (int j = 0; j < 8; j++) {
            cO[j][0] *= f0; cO[j][1] *= f0;
            cO[j][2] *= f1; cO[j][3] *= f1;
        }

        // O += P * V (fp16 mma; P frags direct from cS layout)
        #pragma unroll
        for (int tk = 0; tk < 4; tk++) {
            uint32_t aP[4] = { ph[2*tk][0], ph[2*tk][1],
                               ph[2*tk+1][0], ph[2*tk+1][1] };
            #pragma unroll
            for (int jp = 0; jp < 4; jp++) {
                const int vrow = tk * 16 + (lane & 15);
                const int vcol = (lane >> 4) * 8 + jp * 16;
                uint32_t addr = vsb + (uint32_t)(vrow * 72 + vcol) * 2u;
                uint32_t r0, r1, r2, r3;
                ldmatrix_x4_trans(r0, r1, r2, r3, addr);
                mma_f16(cO[2*jp    ], aP, r0, r1);
                mma_f16(cO[2*jp + 1], aP, r2, r3);
            }
        }
        __syncthreads();
    }

    // Epilogue: normalize, write fp16 to concat layout [B*SQ, D]
    const float inv0 = 1.f / l0;
    const float inv1 = 1.f / l1;
    const int qrow = qt * 128 + w16 + gid;
    __half* op0 = g_C + ((size_t)(b * SQ_ + qrow)) * D_ + h * HD_;
    __half* op1 = op0 + (size_t)8 * D_;
    #pragma unroll
    for (int j = 0; j < 8; j++) {
        const int nl = j * 8 + tid4 * 2;
        uint32_t v0 = packh2(cO[j][0] * inv0, cO[j][1] * inv0);
        uint32_t v1 = packh2(cO[j][2] * inv1, cO[j][3] * inv1);
        *(uint32_t*)&op0[nl] = v0;
        *(uint32_t*)&op1[nl] = v1;
    }
}

// ---------------------------------------------------------------------------
extern "C" void kernel_launch(void* const* d_in, const int* in_sizes, int n_in,
                              void* d_out, int out_size)
{
    const float* x   = (const float*)d_in[0];
    const float* enc = (const float*)d_in[1];
    const float* Wq  = (const float*)d_in[2];
    const float* bq  = (const float*)d_in[3];
    const float* Wk  = (const float*)d_in[4];
    const float* bk  = (const float*)d_in[5];
    const float* Wv  = (const float*)d_in[6];
    const float* bv  = (const float*)d_in[7];
    const float* Wo  = (const float*)d_in[8];
    const float* bo  = (const float*)d_in[9];

    __half *xh, *eh, *Wqh, *Wkh, *Wvh, *Woh, *Qp, *Kp, *Vp, *Cp;
    cudaGetSymbolAddress((void**)&xh,  g_xh);
    cudaGetSymbolAddress((void**)&eh,  g_eh);
    cudaGetSymbolAddress((void**)&Wqh, g_Wqh);
    cudaGetSymbolAddress((void**)&Wkh, g_Wkh);
    cudaGetSymbolAddress((void**)&Wvh, g_Wvh);
    cudaGetSymbolAddress((void**)&Woh, g_Woh);
    cudaGetSymbolAddress((void**)&Qp,  g_Q);
    cudaGetSymbolAddress((void**)&Kp,  g_K);
    cudaGetSymbolAddress((void**)&Vp,  g_V);
    cudaGetSymbolAddress((void**)&Cp,  g_C);

    // Prepass: fp16 activations + transposed fp16 weights
    cvt_f2h<<<(MTOT*D_/4)/256, 256>>>(x,   xh);
    cvt_f2h<<<(MTOT*D_/4)/256, 256>>>(enc, eh);
    tr_cvt<<<dim3(HD_/32, D_/32, H_), 256>>>(Wq, Wqh, D_, HD_);
    tr_cvt<<<dim3(HD_/32, D_/32, H_), 256>>>(Wk, Wkh, D_, HD_);
    tr_cvt<<<dim3(HD_/32, D_/32, H_), 256>>>(Wv, Wvh, D_, HD_);
    tr_cvt<<<dim3(D_/32,  D_/32, 1 ), 256>>>(Wo, Woh, D_, D_);

    dim3 gthr(256);
    dim3 ggrid(16, MTOT / 128);   // (16, 32)

    gemm_h<0><<<ggrid, gthr>>>(xh, Wqh, bq, Qp, QSCALE);
    gemm_h<0><<<ggrid, gthr>>>(eh, Wkh, bk, Kp, 1.f);
    gemm_h<0><<<ggrid, gthr>>>(eh, Wvh, bv, Vp, 1.f);

    flash_h<<<dim3(SQ_/128, H_, B_), 256>>>();

    gemm_h<1><<<ggrid, gthr>>>(Cp, Woh, bo, d_out, 1.f);
}

// round 10
// speedup vs baseline: 9.7750x; 1.2197x over previous
#include <cuda_runtime.h>
#include <cuda_fp16.h>
#include <cstdint>
#include <math.h>

#define B_   2
#define SQ_  2048
#define SK_  2048
#define D_   1024
#define H_   16
#define HD_  64
#define MTOT (B_*SQ_)   // 4096

#define QSCALE (0.125f * 1.4426950408889634f)   // softmax scale * log2(e)

// ---------------------------------------------------------------------------
// fp16 scratch (allocation-free rule: __device__ globals)
// ---------------------------------------------------------------------------
__device__ __half g_xh  [MTOT*D_];        // x in fp16
__device__ __half g_eh  [MTOT*D_];        // encoder_output in fp16
__device__ __half g_Wqh [H_*HD_*D_];      // [n][k] fp16 (n = h*64+e)
__device__ __half g_Wkvh[2*H_*HD_*D_];    // rows 0..1023 = Wk, 1024..2047 = Wv
__device__ __half g_Woh [D_*D_];          // [n][k] fp16
__device__ __half g_Q   [B_*H_*SQ_*HD_];  // [B,H,SQ,HD], pre-scaled by QSCALE
__device__ __half g_K   [B_*H_*SK_*HD_];
__device__ __half g_V   [B_*H_*SK_*HD_];
__device__ __half g_C   [B_*SQ_*D_];      // concat attention out [B*SQ, D]

// ---------------------------------------------------------------------------
// helpers
// ---------------------------------------------------------------------------
__device__ __forceinline__ uint32_t smem_u32(const void* p) {
    uint32_t a;
    asm("{ .reg .u64 t; cvta.to.shared.u64 t, %1; cvt.u32.u64 %0, t; }"
        : "=r"(a) : "l"(p));
    return a;
}

__device__ __forceinline__ void mma_f16(float c[4], const uint32_t a[4],
                                        uint32_t b0, uint32_t b1) {
    asm volatile(
        "mma.sync.aligned.m16n8k16.row.col.f32.f16.f16.f32 "
        "{%0,%1,%2,%3}, {%4,%5,%6,%7}, {%8,%9}, {%0,%1,%2,%3};"
        : "+f"(c[0]), "+f"(c[1]), "+f"(c[2]), "+f"(c[3])
        : "r"(a[0]), "r"(a[1]), "r"(a[2]), "r"(a[3]), "r"(b0), "r"(b1));
}

__device__ __forceinline__ void ldmatrix_x4_trans(uint32_t& r0, uint32_t& r1,
                                                  uint32_t& r2, uint32_t& r3,
                                                  uint32_t addr) {
    asm volatile(
        "ldmatrix.sync.aligned.m8n8.x4.trans.shared.b16 {%0,%1,%2,%3}, [%4];"
        : "=r"(r0), "=r"(r1), "=r"(r2), "=r"(r3) : "r"(addr));
}

__device__ __forceinline__ void cp16(uint32_t dst, const void* src) {
    asm volatile("cp.async.ca.shared.global [%0], [%1], 16;\n"
                 :: "r"(dst), "l"(src));
}
__device__ __forceinline__ void cp_commit() {
    asm volatile("cp.async.commit_group;\n");
}
template<int N> __device__ __forceinline__ void cp_wait() {
    asm volatile("cp.async.wait_group %0;\n" :: "n"(N));
}

__device__ __forceinline__ float ex2(float x) {
    float r;
    asm("ex2.approx.f32 %0, %1;" : "=f"(r) : "f"(x));
    return r;
}

__device__ __forceinline__ uint32_t packh2(float a, float b) {
    __half2 h = __floats2half2_rn(a, b);
    return *reinterpret_cast<uint32_t*>(&h);
}

// ---------------------------------------------------------------------------
// prepass 1: f32 -> fp16 elementwise
// ---------------------------------------------------------------------------
__global__ __launch_bounds__(256)
void cvt_f2h(const float* __restrict__ in, __half* __restrict__ out) {
    const int i = blockIdx.x * 256 + threadIdx.x;
    float4 v = ((const float4*)in)[i];
    uint2 u;
    u.x = packh2(v.x, v.y);
    u.y = packh2(v.z, v.w);
    ((uint2*)out)[i] = u;
}

// ---------------------------------------------------------------------------
// prepass 2: transpose + convert. in f32 [R,C] -> out fp16 [C,R].
// grid (C/32, R/32, Z); per-z input offset R*C, output offset R*C.
// ---------------------------------------------------------------------------
__global__ __launch_bounds__(256)
void tr_cvt(const float* __restrict__ in, __half* __restrict__ out,
            int R, int C) {
    __shared__ float tile[32][33];
    in  += (size_t)blockIdx.z * R * C;
    out += (size_t)blockIdx.z * R * C;
    const int c0 = blockIdx.x * 32, r0 = blockIdx.y * 32;
    const int tx = threadIdx.x & 31, ty = threadIdx.x >> 5;
    #pragma unroll
    for (int i = 0; i < 32; i += 8)
        tile[ty + i][tx] = in[(size_t)(r0 + ty + i) * C + c0 + tx];
    __syncthreads();
    #pragma unroll
    for (int i = 0; i < 32; i += 8)
        out[(size_t)(c0 + ty + i) * R + r0 + tx] =
            __float2half_rn(tile[tx][ty + i]);
}

// ---------------------------------------------------------------------------
// fp16 mma GEMM v2: tile 128x128, 8 warps (warp = 16 rows x 128 cols),
// BK=64, double-buffered cp.async, dynamic smem 72KB.
// A fp16 [M,1024] row-major; Wh fp16 [n][k] (N rows total = 128*gridDim.x).
// EPI 0 (headed half out): tile bx<8 -> out0/bias0, else out1/bias1 with
//   column nb=(bx&7)*128; head = nf>>6; value (acc+bias)*scale.
// EPI 1 (flat f32 out): out0[m*D + bx*128+nl] = acc+bias0.
// smem row = 64 halfs + pad = 36 words (conflict-free: gid*36 mod 32 = gid*4).
// ---------------------------------------------------------------------------
#define RSW 36                       // words per smem row
#define BUFW (128 * RSW)             // words per operand buffer (4608)
#define G2_SMEM (4 * BUFW * 4)       // 73,728 B

template<int EPI>
__global__ __launch_bounds__(256)
void gemm2(const __half* __restrict__ A, const __half* __restrict__ Wh,
           const float* __restrict__ bias0, const float* __restrict__ bias1,
           void* __restrict__ out0, void* __restrict__ out1, float scale)
{
    extern __shared__ uint32_t sm2[];
    // layout: [buf0: A | W][buf1: A | W], each operand BUFW words
    const int t    = threadIdx.x;
    const int lane = t & 31, wid = t >> 5;
    const int gid  = lane >> 2, tid4 = lane & 3;
    const int w16  = wid * 16;
    const int bx   = blockIdx.x;
    const int m0   = blockIdx.y * 128;

    const __half* Wb = Wh + (size_t)bx * 128 * D_;
    const uint32_t smb = smem_u32(sm2);

    auto stage = [&](int kc) {
        const uint32_t ab = smb + (uint32_t)(kc & 1) * (2 * BUFW * 4);
        const uint32_t wb = ab + BUFW * 4;
        const int k0 = kc * 64;
        #pragma unroll
        for (int it = 0; it < 4; it++) {
            const int id  = t + it * 256;            // 0..1023
            const int row = id >> 3, ch = id & 7;    // 128 rows x 8 16B-chunks
            const uint32_t off = (uint32_t)(row * RSW + ch * 4) * 4;
            cp16(ab + off, A  + (size_t)(m0 + row) * D_ + k0 + ch * 8);
            cp16(wb + off, Wb + (size_t)row        * D_ + k0 + ch * 8);
        }
    };

    float c[16][4];
    #pragma unroll
    for (int j = 0; j < 16; j++)
        #pragma unroll
        for (int i = 0; i < 4; i++) c[j][i] = 0.f;

    stage(0); cp_commit();

    for (int kc = 0; kc < 16; kc++) {
        if (kc + 1 < 16) { stage(kc + 1); cp_commit(); cp_wait<1>(); }
        else             { cp_wait<0>(); }
        __syncthreads();

        const uint32_t* Ab = sm2 + (kc & 1) * 2 * BUFW;
        const uint32_t* Bb = Ab + BUFW;
        #pragma unroll
        for (int ks = 0; ks < 4; ks++) {
            uint32_t a[4];
            a[0] = Ab[(w16 + gid    ) * RSW + ks * 8 + tid4    ];
            a[1] = Ab[(w16 + gid + 8) * RSW + ks * 8 + tid4    ];
            a[2] = Ab[(w16 + gid    ) * RSW + ks * 8 + tid4 + 4];
            a[3] = Ab[(w16 + gid + 8) * RSW + ks * 8 + tid4 + 4];
            #pragma unroll
            for (int j = 0; j < 16; j++) {
                uint32_t b0 = Bb[(j * 8 + gid) * RSW + ks * 8 + tid4    ];
                uint32_t b1 = Bb[(j * 8 + gid) * RSW + ks * 8 + tid4 + 4];
                mma_f16(c[j], a, b0, b1);
            }
        }
        __syncthreads();
    }

    // Epilogue
    if (EPI == 0) {
        __half* outH      = (bx < 8) ? (__half*)out0 : (__half*)out1;
        const float* bs   = (bx < 8) ? bias0 : bias1;
        const int nb      = (bx & 7) * 128;
        #pragma unroll
        for (int hh = 0; hh < 2; hh++) {
            const int m  = m0 + w16 + gid + hh * 8;
            const int bI = m >> 11, s = m & 2047;
            #pragma unroll
            for (int j = 0; j < 16; j++) {
                const int nf = nb + j * 8 + tid4 * 2;
                const float v0 = c[j][hh * 2 + 0] + bs[nf];
                const float v1 = c[j][hh * 2 + 1] + bs[nf + 1];
                const int head = nf >> 6, nl = nf & 63;
                *(uint32_t*)&outH[(((size_t)(bI * H_ + head)) * SQ_ + s) * HD_ + nl] =
                    packh2(v0 * scale, v1 * scale);
            }
        }
    } else {
        float* out = (float*)out0;
        #pragma unroll
        for (int hh = 0; hh < 2; hh++) {
            const int m = m0 + w16 + gid + hh * 8;
            #pragma unroll
            for (int j = 0; j < 16; j++) {
                const int nf = bx * 128 + j * 8 + tid4 * 2;
                const float v0 = c[j][hh * 2 + 0] + bias0[nf];
                const float v1 = c[j][hh * 2 + 1] + bias0[nf + 1];
                *(float2*)&out[(size_t)m * D_ + nf] = make_float2(v0, v1);
            }
        }
    }
}

// ---------------------------------------------------------------------------
// Flash attention, fp16 mma (unchanged, proven). Block = (b,h,128 q rows).
// ---------------------------------------------------------------------------
__global__ __launch_bounds__(256)
void flash_h()
{
    __shared__ uint32_t pool[9216];   // 36,864 B

    const int t    = threadIdx.x;
    const int lane = t & 31, wid = t >> 5;
    const int gid  = lane >> 2, tid4 = lane & 3;
    const int w16  = wid * 16;

    const int qt = blockIdx.x;
    const int h  = blockIdx.y;
    const int b  = blockIdx.z;

    const size_t qbase  = (((size_t)b * H_ + h) * SQ_ + qt * 128) * HD_;
    const size_t kvbase = (((size_t)b * H_ + h) * SK_) * HD_;

    const uint32_t pb = smem_u32(pool);

    #pragma unroll
    for (int it = 0; it < 4; it++) {
        const int id  = t + it * 256;
        const int row = id >> 3, c8 = (id & 7) * 8;
        cp16(pb + (uint32_t)(row * 36 + (id & 7) * 4) * 4,
             g_Q + qbase + (size_t)row * HD_ + c8);
    }
    cp_commit(); cp_wait<0>();
    __syncthreads();

    uint32_t aQ[4][4];
    #pragma unroll
    for (int ks = 0; ks < 4; ks++) {
        aQ[ks][0] = pool[(w16 + gid    ) * 36 + ks * 8 + tid4    ];
        aQ[ks][1] = pool[(w16 + gid + 8) * 36 + ks * 8 + tid4    ];
        aQ[ks][2] = pool[(w16 + gid    ) * 36 + ks * 8 + tid4 + 4];
        aQ[ks][3] = pool[(w16 + gid + 8) * 36 + ks * 8 + tid4 + 4];
    }
    __syncthreads();

    float cO[8][4];
    #pragma unroll
    for (int j = 0; j < 8; j++)
        #pragma unroll
        for (int i = 0; i < 4; i++) cO[j][i] = 0.f;
    float m0 = -1e30f, m1 = -1e30f, l0 = 0.f, l1 = 0.f;

    auto stageKV = [&](int buf, int c0) {
        #pragma unroll
        for (int it = 0; it < 2; it++) {
            const int id  = t + it * 256;
            const int row = id >> 3, c8 = (id & 7) * 8;
            const size_t go = kvbase + (size_t)(c0 + row) * HD_ + c8;
            cp16(pb + (uint32_t)(       buf * 2304 + row * 36 + (id & 7) * 4) * 4,
                 g_K + go);
            cp16(pb + (uint32_t)(4608 + buf * 2304 + row * 36 + (id & 7) * 4) * 4,
                 g_V + go);
        }
    };

    stageKV(0, 0);
    cp_commit();

    for (int cc = 0; cc < 32; cc++) {
        if (cc + 1 < 32) { stageKV((cc + 1) & 1, (cc + 1) * 64); cp_commit(); cp_wait<1>(); }
        else             { cp_wait<0>(); }
        __syncthreads();

        const uint32_t* Ks = pool + (cc & 1) * 2304;
        const uint32_t  vsb = pb + (uint32_t)(4608 + (cc & 1) * 2304) * 4;

        float cS[8][4];
        #pragma unroll
        for (int j = 0; j < 8; j++)
            #pragma unroll
            for (int i = 0; i < 4; i++) cS[j][i] = 0.f;

        #pragma unroll
        for (int ks = 0; ks < 4; ks++) {
            #pragma unroll
            for (int j = 0; j < 8; j++) {
                uint32_t b0 = Ks[(j * 8 + gid) * 36 + ks * 8 + tid4    ];
                uint32_t b1 = Ks[(j * 8 + gid) * 36 + ks * 8 + tid4 + 4];
                mma_f16(cS[j], aQ[ks], b0, b1);
            }
        }

        float mx0 = -1e30f, mx1 = -1e30f;
        #pragma unroll
        for (int j = 0; j < 8; j++) {
            mx0 = fmaxf(mx0, fmaxf(cS[j][0], cS[j][1]));
            mx1 = fmaxf(mx1, fmaxf(cS[j][2], cS[j][3]));
        }
        mx0 = fmaxf(mx0, __shfl_xor_sync(0xffffffffu, mx0, 1));
        mx0 = fmaxf(mx0, __shfl_xor_sync(0xffffffffu, mx0, 2));
        mx1 = fmaxf(mx1, __shfl_xor_sync(0xffffffffu, mx1, 1));
        mx1 = fmaxf(mx1, __shfl_xor_sync(0xffffffffu, mx1, 2));
        const float nm0 = fmaxf(m0, mx0), nm1 = fmaxf(m1, mx1);
        const float f0 = ex2(m0 - nm0), f1 = ex2(m1 - nm1);
        m0 = nm0; m1 = nm1;

        float s0 = 0.f, s1 = 0.f;
        uint32_t ph[8][2];
        #pragma unroll
        for (int j = 0; j < 8; j++) {
            const float p0 = ex2(cS[j][0] - m0);
            const float p1 = ex2(cS[j][1] - m0);
            const float p2 = ex2(cS[j][2] - m1);
            const float p3 = ex2(cS[j][3] - m1);
            s0 += p0 + p1;  s1 += p2 + p3;
            ph[j][0] = packh2(p0, p1);
            ph[j][1] = packh2(p2, p3);
        }
        s0 += __shfl_xor_sync(0xffffffffu, s0, 1);
        s0 += __shfl_xor_sync(0xffffffffu, s0, 2);
        s1 += __shfl_xor_sync(0xffffffffu, s1, 1);
        s1 += __shfl_xor_sync(0xffffffffu, s1, 2);
        l0 = l0 * f0 + s0;
        l1 = l1 * f1 + s1;

        #pragma unroll
        for (int j = 0; j < 8; j++) {
            cO[j][0] *= f0; cO[j][1] *= f0;
            cO[j][2] *= f1; cO[j][3] *= f1;
        }

        #pragma unroll
        for (int tk = 0; tk < 4; tk++) {
            uint32_t aP[4] = { ph[2*tk][0], ph[2*tk][1],
                               ph[2*tk+1][0], ph[2*tk+1][1] };
            #pragma unroll
            for (int jp = 0; jp < 4; jp++) {
                const int vrow = tk * 16 + (lane & 15);
                const int vcol = (lane >> 4) * 8 + jp * 16;
                uint32_t addr = vsb + (uint32_t)(vrow * 72 + vcol) * 2u;
                uint32_t r0, r1, r2, r3;
                ldmatrix_x4_trans(r0, r1, r2, r3, addr);
                mma_f16(cO[2*jp    ], aP, r0, r1);
                mma_f16(cO[2*jp + 1], aP, r2, r3);
            }
        }
        __syncthreads();
    }

    const float inv0 = 1.f / l0;
    const float inv1 = 1.f / l1;
    const int qrow = qt * 128 + w16 + gid;
    __half* op0 = g_C + ((size_t)(b * SQ_ + qrow)) * D_ + h * HD_;
    __half* op1 = op0 + (size_t)8 * D_;
    #pragma unroll
    for (int j = 0; j < 8; j++) {
        const int nl = j * 8 + tid4 * 2;
        *(uint32_t*)&op0[nl] = packh2(cO[j][0] * inv0, cO[j][1] * inv0);
        *(uint32_t*)&op1[nl] = packh2(cO[j][2] * inv1, cO[j][3] * inv1);
    }
}

// ---------------------------------------------------------------------------
extern "C" void kernel_launch(void* const* d_in, const int* in_sizes, int n_in,
                              void* d_out, int out_size)
{
    const float* x   = (const float*)d_in[0];
    const float* enc = (const float*)d_in[1];
    const float* Wq  = (const float*)d_in[2];
    const float* bq  = (const float*)d_in[3];
    const float* Wk  = (const float*)d_in[4];
    const float* bk  = (const float*)d_in[5];
    const float* Wv  = (const float*)d_in[6];
    const float* bv  = (const float*)d_in[7];
    const float* Wo  = (const float*)d_in[8];
    const float* bo  = (const float*)d_in[9];

    __half *xh, *eh, *Wqh, *Wkvh, *Woh, *Qp, *Kp, *Vp, *Cp;
    cudaGetSymbolAddress((void**)&xh,   g_xh);
    cudaGetSymbolAddress((void**)&eh,   g_eh);
    cudaGetSymbolAddress((void**)&Wqh,  g_Wqh);
    cudaGetSymbolAddress((void**)&Wkvh, g_Wkvh);
    cudaGetSymbolAddress((void**)&Woh,  g_Woh);
    cudaGetSymbolAddress((void**)&Qp,   g_Q);
    cudaGetSymbolAddress((void**)&Kp,   g_K);
    cudaGetSymbolAddress((void**)&Vp,   g_V);
    cudaGetSymbolAddress((void**)&Cp,   g_C);

    // Prepass: fp16 activations + transposed fp16 weights (K,V fused)
    cvt_f2h<<<(MTOT*D_/4)/256, 256>>>(x,   xh);
    cvt_f2h<<<(MTOT*D_/4)/256, 256>>>(enc, eh);
    tr_cvt<<<dim3(HD_/32, D_/32, H_), 256>>>(Wq, Wqh, D_, HD_);
    tr_cvt<<<dim3(HD_/32, D_/32, H_), 256>>>(Wk, Wkvh, D_, HD_);
    tr_cvt<<<dim3(HD_/32, D_/32, H_), 256>>>(Wv, Wkvh + (size_t)D_*D_, D_, HD_);
    tr_cvt<<<dim3(D_/32,  D_/32, 1 ), 256>>>(Wo, Woh, D_, D_);

    cudaFuncSetAttribute(gemm2<0>, cudaFuncAttributeMaxDynamicSharedMemorySize,
                         G2_SMEM);
    cudaFuncSetAttribute(gemm2<1>, cudaFuncAttributeMaxDynamicSharedMemorySize,
                         G2_SMEM);

    // Q projection: N=1024 (8 tiles)
    gemm2<0><<<dim3(8, MTOT/128), 256, G2_SMEM>>>(xh, Wqh, bq, bq, Qp, Qp, QSCALE);
    // K+V fused: N=2048 (16 tiles; bx<8 -> K, bx>=8 -> V)
    gemm2<0><<<dim3(16, MTOT/128), 256, G2_SMEM>>>(eh, Wkvh, bk, bv, Kp, Vp, 1.f);

    flash_h<<<dim3(SQ_/128, H_, B_), 256>>>();

    // Output projection: f32 into d_out
    gemm2<1><<<dim3(8, MTOT/128), 256, G2_SMEM>>>(Cp, Woh, bo, bo, d_out, d_out, 1.f);
}